// round 16
// baseline (speedup 1.0000x reference)
#include <cuda_runtime.h>
#include <cuda_fp16.h>

#define NN 40000
#define EE 640000
#define HD 128
#define GG 64
#define PADH 136   // padded halves per smem row (conflict-free ldmatrix)

// ---------------- scratch (no allocs: __device__ globals) -------------------
__device__ __align__(16) float  g_xw  [(size_t)NN * HD];   // x@W f32
__device__ __align__(16) __half g_xwh [(size_t)NN * HD];   // x@W fp16 (gather)
__device__ __align__(16) __half g_aggh[(size_t)NN * HD];   // fp16 edge accum
__device__ __align__(16) __half g_hh  [(size_t)NN * HD];   // layer output fp16
__device__ __align__(16) int    g_degi[NN];
__device__ __align__(16) float  g_dinv[NN];
__device__ __align__(16) int    g_src [EE];
__device__ __align__(16) int    g_dst [EE];
__device__ __align__(16) int    g_adj [EE];                // src, dst-sorted
__device__ __align__(16) int    g_dsts[EE];                // dst, dst-sorted
__device__ __align__(16) int    g_rowstart[NN + 1];
__device__ __align__(16) int    g_cursor[NN];
__device__ __align__(16) int    g_gstart[GG + 1];
__device__ __align__(16) float  g_pool[GG * HD];
__device__ int g_is64;

__device__ __forceinline__ int IDX(const void* p, long long pos) {
    return g_is64 ? (int)((const long long*)p)[pos] : ((const int*)p)[pos];
}

// ---------------- dtype detection (reads first 32KB only) -------------------
__global__ void detect_kernel(const unsigned int* __restrict__ raw) {
    __shared__ int nz;
    if (threadIdx.x == 0) nz = 0;
    __syncthreads();
    int cnt = 0;
    for (int j = threadIdx.x; j < 4096; j += 256)
        if (raw[2 * j + 1] != 0u) cnt++;
    atomicAdd(&nz, cnt);
    __syncthreads();
    if (threadIdx.x == 0) g_is64 = (nz < 64) ? 1 : 0;
}

// ---------------- prep ------------------------------------------------------
// index convert + in-degree histogram (+ gstart init folded in)
__global__ void conv_deg_kernel(const void* __restrict__ ei) {
    int i = blockIdx.x * blockDim.x + threadIdx.x;
    if (i <= GG) g_gstart[i] = NN;
    if (i >= EE) return;
    int s = IDX(ei, i);
    int d = IDX(ei, (long long)EE + i);
    g_src[i] = s;
    g_dst[i] = d;
    atomicAdd(&g_degi[d], 1);
}

// single-block exclusive prefix sum over g_degi -> g_rowstart
__global__ __launch_bounds__(1024) void prefix_kernel() {
    int t = threadIdx.x;
    int base = t * 40;                 // 1024*40 >= 40000
    int s = 0;
    for (int j = 0; j < 40; j++) {
        int idx = base + j;
        if (idx < NN) s += g_degi[idx];
    }
    int lane = t & 31, wid = t >> 5;
    int v = s;
#pragma unroll
    for (int o = 1; o < 32; o <<= 1) {
        int u = __shfl_up_sync(~0u, v, o);
        if (lane >= o) v += u;
    }
    __shared__ int ws[32];
    if (lane == 31) ws[wid] = v;
    __syncthreads();
    if (wid == 0) {
        int w = ws[lane];
#pragma unroll
        for (int o = 1; o < 32; o <<= 1) {
            int u = __shfl_up_sync(~0u, w, o);
            if (lane >= o) w += u;
        }
        ws[lane] = w;
    }
    __syncthreads();
    int run = v - s + (wid ? ws[wid - 1] : 0);
    for (int j = 0; j < 40; j++) {
        int idx = base + j;
        if (idx < NN) { g_rowstart[idx] = run; run += g_degi[idx]; }
    }
    if (t == 0) g_rowstart[NN] = EE;
}

__global__ void dinv_kernel() {
    int i = blockIdx.x * blockDim.x + threadIdx.x;
    if (i < NN) g_dinv[i] = rsqrtf((float)g_degi[i] + 1.0f);
}

// graph boundaries from sorted batch (no atomics)
__global__ void gstart_kernel(const void* __restrict__ batch) {
    int i = blockIdx.x * blockDim.x + threadIdx.x;
    if (i >= NN) return;
    int b  = IDX(batch, i);
    int bp = i ? IDX(batch, i - 1) : -1;
    for (int g = bp + 1; g <= b; g++) g_gstart[g] = i;
}

// scatter edges into dst-sorted order
__global__ void scatter_kernel() {
    int i = blockIdx.x * blockDim.x + threadIdx.x;
    if (i >= EE) return;
    int d = g_dst[i];
    int pos = g_rowstart[d] + atomicAdd(&g_cursor[d], 1);
    g_adj[pos]  = g_src[i];
    g_dsts[pos] = d;
}

// ---------------- tensor-core GEMM: C[M,128] = A[M,128] @ W[128,128] --------
// a_is_half: A is fp16 (g_hh), raw-copy tile fill; else f32 + convert.
__global__ __launch_bounds__(256) void gemm_tc_kernel(const void* __restrict__ A,
                                                      const float* __restrict__ W,
                                                      int a_is_half) {
    extern __shared__ __half smh[];
    __half* As = smh;                 // [128][PADH]
    __half* Bs = smh + 128 * PADH;    // [128][PADH]  (Bs[k][n])

    int tid = threadIdx.x;
    long long mbase = (long long)blockIdx.x * 128;

    if (a_is_half) {
#pragma unroll
        for (int i = 0; i < 16; i++) {
            int idx = i * 256 + tid;
            int row = idx >> 5, c4 = idx & 31;
            long long grow = mbase + row;
            uint2 v = (grow < NN) ? ((const uint2*)A)[grow * 32 + c4]
                                  : make_uint2(0u, 0u);
            *(uint2*)(As + row * PADH + c4 * 4) = v;
        }
    } else {
#pragma unroll
        for (int i = 0; i < 16; i++) {
            int idx = i * 256 + tid;
            int row = idx >> 5, c4 = idx & 31;
            long long grow = mbase + row;
            float4 v = (grow < NN) ? ((const float4*)A)[grow * 32 + c4]
                                   : make_float4(0.f, 0.f, 0.f, 0.f);
            __half2* dst = (__half2*)(As + row * PADH + c4 * 4);
            dst[0] = __floats2half2_rn(v.x, v.y);
            dst[1] = __floats2half2_rn(v.z, v.w);
        }
    }
#pragma unroll
    for (int i = 0; i < 16; i++) {
        int idx = i * 256 + tid;
        int row = idx >> 5, c4 = idx & 31;
        float4 v = ((const float4*)W)[row * 32 + c4];
        __half2* dst = (__half2*)(Bs + row * PADH + c4 * 4);
        dst[0] = __floats2half2_rn(v.x, v.y);
        dst[1] = __floats2half2_rn(v.z, v.w);
    }
    __syncthreads();

    int wid = tid >> 5, lane = tid & 31;
    int wm = (wid & 3) * 32;
    int wn = (wid >> 2) * 64;

    float acc[2][8][4];
#pragma unroll
    for (int mt = 0; mt < 2; mt++)
#pragma unroll
        for (int nt = 0; nt < 8; nt++)
#pragma unroll
            for (int q = 0; q < 4; q++) acc[mt][nt][q] = 0.f;

#pragma unroll
    for (int kk = 0; kk < 8; kk++) {
        unsigned a[2][4];
#pragma unroll
        for (int mt = 0; mt < 2; mt++) {
            int r = lane & 15, c = (lane >> 4) * 8;
            unsigned addr = (unsigned)__cvta_generic_to_shared(
                As + (wm + mt * 16 + r) * PADH + kk * 16 + c);
            asm volatile("ldmatrix.sync.aligned.m8n8.x4.shared.b16 {%0,%1,%2,%3}, [%4];"
                         : "=r"(a[mt][0]), "=r"(a[mt][1]), "=r"(a[mt][2]), "=r"(a[mt][3])
                         : "r"(addr));
        }
        unsigned b[8][2];
#pragma unroll
        for (int nt2 = 0; nt2 < 4; nt2++) {
            int krow = kk * 16 + ((lane >> 3) & 1) * 8 + (lane & 7);
            int ncol = wn + nt2 * 16 + (lane >> 4) * 8;
            unsigned addr = (unsigned)__cvta_generic_to_shared(Bs + krow * PADH + ncol);
            asm volatile("ldmatrix.sync.aligned.m8n8.x4.trans.shared.b16 {%0,%1,%2,%3}, [%4];"
                         : "=r"(b[nt2 * 2][0]), "=r"(b[nt2 * 2][1]),
                           "=r"(b[nt2 * 2 + 1][0]), "=r"(b[nt2 * 2 + 1][1])
                         : "r"(addr));
        }
#pragma unroll
        for (int mt = 0; mt < 2; mt++)
#pragma unroll
            for (int nt = 0; nt < 8; nt++)
                asm volatile("mma.sync.aligned.m16n8k16.row.col.f32.f16.f16.f32 "
                             "{%0,%1,%2,%3}, {%4,%5,%6,%7}, {%8,%9}, {%0,%1,%2,%3};"
                             : "+f"(acc[mt][nt][0]), "+f"(acc[mt][nt][1]),
                               "+f"(acc[mt][nt][2]), "+f"(acc[mt][nt][3])
                             : "r"(a[mt][0]), "r"(a[mt][1]), "r"(a[mt][2]), "r"(a[mt][3]),
                               "r"(b[nt][0]), "r"(b[nt][1]));
    }

    int r0 = lane >> 2, cq = (lane & 3) * 2;
#pragma unroll
    for (int mt = 0; mt < 2; mt++) {
        long long rowA = mbase + wm + mt * 16 + r0;
        long long rowB = rowA + 8;
#pragma unroll
        for (int nt = 0; nt < 8; nt++) {
            int col = wn + nt * 8 + cq;
            if (rowA < NN) {
                *(float2*)&g_xw[rowA * HD + col] = make_float2(acc[mt][nt][0], acc[mt][nt][1]);
                *(__half2*)&g_xwh[rowA * HD + col] = __floats2half2_rn(acc[mt][nt][0], acc[mt][nt][1]);
            }
            if (rowB < NN) {
                *(float2*)&g_xw[rowB * HD + col] = make_float2(acc[mt][nt][2], acc[mt][nt][3]);
                *(__half2*)&g_xwh[rowB * HD + col] = __floats2half2_rn(acc[mt][nt][2], acc[mt][nt][3]);
            }
        }
    }
}

// ---------------- paired edge scatter (dst-sorted, no serial loop) ----------
// One 16-lane group handles edges (2g, 2g+1). Both gathers issue independently
// (MLP=2). Same dst (~94% at mean degree 16) -> f32 combine, ONE RED; else two.
__global__ __launch_bounds__(256) void edge_pair_kernel() {
    long long t = (long long)blockIdx.x * 256 + threadIdx.x;
    int grp = (int)(t >> 4);                 // EE/2 groups
    if (grp >= EE / 2) return;
    int sub = threadIdx.x & 15;
    int e0 = grp * 2, e1 = e0 + 1;

    int s0 = __ldg(&g_adj[e0]);
    int s1 = __ldg(&g_adj[e1]);
    int d0 = __ldg(&g_dsts[e0]);
    int d1 = __ldg(&g_dsts[e1]);
    // both gathers in flight before any math
    uint4 v0 = ((const uint4*)g_xwh)[(size_t)s0 * 16 + sub];
    uint4 v1 = ((const uint4*)g_xwh)[(size_t)s1 * 16 + sub];
    float nm0 = __ldg(&g_dinv[d0]) * __ldg(&g_dinv[s0]);
    float nm1 = __ldg(&g_dinv[d1]) * __ldg(&g_dinv[s1]);

    __half2* h0 = (__half2*)&v0;
    __half2* h1 = (__half2*)&v1;

    if (d0 == d1) {
        uint4 o;
        __half2* ho = (__half2*)&o;
#pragma unroll
        for (int i = 0; i < 4; i++) {
            float2 f0 = __half22float2(h0[i]);
            float2 f1 = __half22float2(h1[i]);
            ho[i] = __floats2half2_rn(fmaf(f0.x, nm0, f1.x * nm1),
                                      fmaf(f0.y, nm0, f1.y * nm1));
        }
        __half* p = g_aggh + (size_t)d0 * HD + sub * 8;
        asm volatile("red.global.add.noftz.v4.f16x2 [%0], {%1,%2,%3,%4};"
                     :: "l"(p), "r"(o.x), "r"(o.y), "r"(o.z), "r"(o.w)
                     : "memory");
    } else {
        uint4 a, b;
        __half2* ha = (__half2*)&a;
        __half2* hb = (__half2*)&b;
#pragma unroll
        for (int i = 0; i < 4; i++) {
            float2 f0 = __half22float2(h0[i]);
            float2 f1 = __half22float2(h1[i]);
            ha[i] = __floats2half2_rn(f0.x * nm0, f0.y * nm0);
            hb[i] = __floats2half2_rn(f1.x * nm1, f1.y * nm1);
        }
        __half* p0 = g_aggh + (size_t)d0 * HD + sub * 8;
        __half* p1 = g_aggh + (size_t)d1 * HD + sub * 8;
        asm volatile("red.global.add.noftz.v4.f16x2 [%0], {%1,%2,%3,%4};"
                     :: "l"(p0), "r"(a.x), "r"(a.y), "r"(a.z), "r"(a.w)
                     : "memory");
        asm volatile("red.global.add.noftz.v4.f16x2 [%0], {%1,%2,%3,%4};"
                     :: "l"(p1), "r"(b.x), "r"(b.y), "r"(b.z), "r"(b.w)
                     : "memory");
    }
}

// ---------------- node epilogue: hh = relu(aggh + xw*dinv^2 + b) (fp16 out) -
__global__ void node_kernel(const float* __restrict__ b) {
    int i = blockIdx.x * blockDim.x + threadIdx.x;   // over NN*32 float4s
    int node = i >> 5, q = i & 31;
    float di = g_dinv[node];
    float d2 = di * di;
    uint2 av = ((const uint2*)g_aggh)[i];
    float2 a0 = __half22float2(*(__half2*)&av.x);
    float2 a1 = __half22float2(*(__half2*)&av.y);
    float4 w  = ((const float4*)g_xw)[i];
    float4 bb = ((const float4*)b)[q];
    float hx = fmaxf(fmaf(w.x, d2, a0.x) + bb.x, 0.f);
    float hy = fmaxf(fmaf(w.y, d2, a0.y) + bb.y, 0.f);
    float hz = fmaxf(fmaf(w.z, d2, a1.x) + bb.z, 0.f);
    float hw = fmaxf(fmaf(w.w, d2, a1.y) + bb.w, 0.f);
    uint2 o;
    *(__half2*)&o.x = __floats2half2_rn(hx, hy);
    *(__half2*)&o.y = __floats2half2_rn(hz, hw);
    ((uint2*)g_hh)[i] = o;
}

// ---------------- mean pool over sorted batch (shared-bin, fp16 reads) ------
#define POOL_BLOCKS 320
#define POOL_NODES  125          // 320 * 125 = 40000
__global__ __launch_bounds__(128) void pool_accum_kernel(const void* __restrict__ batch) {
    __shared__ float sh[GG * HD];        // 32 KB; thread t owns column t
    int t = threadIdx.x;
    for (int i = t; i < GG * HD; i += 128) sh[i] = 0.f;
    __syncthreads();
    int start = blockIdx.x * POOL_NODES;
    for (int n = start; n < start + POOL_NODES; n++) {
        int g = IDX(batch, n);
        sh[g * HD + t] += __half2float(g_hh[(size_t)n * HD + t]);
    }
    __syncthreads();
    for (int i = t; i < GG * HD; i += 128) atomicAdd(&g_pool[i], sh[i]);
}

__global__ void pool_final_kernel(float* __restrict__ out) {
    int i = blockIdx.x * blockDim.x + threadIdx.x;
    if (i >= GG * HD) return;
    int g = i >> 7;
    float c = (float)(g_gstart[g + 1] - g_gstart[g]);
    out[i] = g_pool[i] / fmaxf(c, 1.0f);
}

// ---------------- launch -----------------------------------------------------
extern "C" void kernel_launch(void* const* d_in, const int* in_sizes, int n_in,
                              void* d_out, int out_size) {
    const float *x = 0, *W1 = 0, *b1 = 0, *W2 = 0, *b2 = 0;
    const void  *ei = 0, *batch = 0;
    for (int i = 0; i < n_in; i++) {
        long long sz = in_sizes[i];
        if      (sz == (long long)NN * HD) x = (const float*)d_in[i];
        else if (sz == 2LL * EE)           ei = d_in[i];
        else if (sz == NN)                 batch = d_in[i];
        else if (sz == HD * HD) { if (!W1) W1 = (const float*)d_in[i];
                                  else     W2 = (const float*)d_in[i]; }
        else if (sz == HD)      { if (!b1) b1 = (const float*)d_in[i];
                                  else     b2 = (const float*)d_in[i]; }
    }
    float* out = (float*)d_out;

    static cudaStream_t sA = 0;
    static cudaEvent_t ev0 = 0, ev1 = 0, ev2 = 0, ev3 = 0, evZ = 0;
    static void* aggh_addr = 0;
    static void* hh_addr = 0;
    static void* degi_addr = 0;
    static void* cursor_addr = 0;
    static void* pool_addr = 0;
    if (!sA) {
        cudaStreamCreateWithFlags(&sA, cudaStreamNonBlocking);
        cudaEventCreateWithFlags(&ev0, cudaEventDisableTiming);
        cudaEventCreateWithFlags(&ev1, cudaEventDisableTiming);
        cudaEventCreateWithFlags(&ev2, cudaEventDisableTiming);
        cudaEventCreateWithFlags(&ev3, cudaEventDisableTiming);
        cudaEventCreateWithFlags(&evZ, cudaEventDisableTiming);
        cudaGetSymbolAddress(&aggh_addr, g_aggh);
        cudaGetSymbolAddress(&hh_addr, g_hh);
        cudaGetSymbolAddress(&degi_addr, g_degi);
        cudaGetSymbolAddress(&cursor_addr, g_cursor);
        cudaGetSymbolAddress(&pool_addr, g_pool);
        cudaFuncSetAttribute((const void*)gemm_tc_kernel,
                             cudaFuncAttributeMaxDynamicSharedMemorySize,
                             2 * 128 * PADH * (int)sizeof(__half));
    }

    const int ZBM   = (NN + 255) / 256;       // 157
    const int EB    = (EE + 255) / 256;       // 2500
    const int EDGB  = (EE / 2 * 16) / 256;    // 20000
    const int NODB  = (NN * 32) / 256;        // 5000
    const int GEMMB = (NN + 127) / 128;       // 313
    const int GSM   = 2 * 128 * PADH * (int)sizeof(__half);
    const size_t AGG_BYTES = (size_t)NN * HD * sizeof(__half);

    // fork: sA zeroes everything + runs GEMM1; main runs the sort/prep chain
    cudaEventRecord(ev0, 0);
    cudaStreamWaitEvent(sA, ev0, 0);
    cudaMemsetAsync(degi_addr, 0, NN * sizeof(int), sA);
    cudaMemsetAsync(cursor_addr, 0, NN * sizeof(int), sA);
    cudaMemsetAsync(pool_addr, 0, GG * HD * sizeof(float), sA);
    cudaEventRecord(evZ, sA);                 // degi/cursor/pool zeroed
    cudaMemsetAsync(aggh_addr, 0, AGG_BYTES, sA);
    gemm_tc_kernel<<<GEMMB, 256, GSM, sA>>>(x, W1, 0);
    cudaEventRecord(ev1, sA);

    detect_kernel<<<1, 256>>>((const unsigned int*)ei);
    cudaStreamWaitEvent(0, evZ, 0);
    conv_deg_kernel<<<EB, 256>>>(ei);
    prefix_kernel<<<1, 1024>>>();
    dinv_kernel<<<ZBM, 256>>>();
    gstart_kernel<<<ZBM, 256>>>(batch);
    scatter_kernel<<<EB, 256>>>();

    // join: layer-1 edge phase
    cudaStreamWaitEvent(0, ev1, 0);
    edge_pair_kernel<<<EDGB, 256>>>();
    node_kernel<<<NODB, 256>>>(b1);
    cudaEventRecord(ev2, 0);

    // fork: re-zero accumulator on sA while main stream runs GEMM2 (fp16 A)
    cudaStreamWaitEvent(sA, ev2, 0);
    cudaMemsetAsync(aggh_addr, 0, AGG_BYTES, sA);
    cudaEventRecord(ev3, sA);
    gemm_tc_kernel<<<GEMMB, 256, GSM>>>(hh_addr, W2, 1);

    // join: layer-2 edge phase
    cudaStreamWaitEvent(0, ev3, 0);
    edge_pair_kernel<<<EDGB, 256>>>();
    node_kernel<<<NODB, 256>>>(b2);

    // pool
    pool_accum_kernel<<<POOL_BLOCKS, 128>>>(batch);
    pool_final_kernel<<<(GG * HD + 255) / 256, 256>>>(out);
}

// round 17
// speedup vs baseline: 1.4619x; 1.4619x over previous
#include <cuda_runtime.h>
#include <cuda_fp16.h>

#define NN 40000
#define EE 640000
#define HD 128
#define GG 64
#define PADH 136   // padded halves per smem row (conflict-free ldmatrix)

// ---------------- scratch (no allocs: __device__ globals) -------------------
__device__ __align__(16) float  g_xw  [(size_t)NN * HD];   // x@W f32
__device__ __align__(16) __half g_xwh [(size_t)NN * HD];   // x@W fp16 (gather)
__device__ __align__(16) __half g_aggh[(size_t)NN * HD];   // fp16 edge accum
__device__ __align__(16) __half g_hh  [(size_t)NN * HD];   // layer output fp16
__device__ __align__(16) int    g_degi[NN];
__device__ __align__(16) float  g_dinv[NN];
__device__ __align__(16) int    g_src [EE];
__device__ __align__(16) int    g_dst [EE];
__device__ __align__(16) int    g_gstart[GG + 1];
__device__ __align__(16) float  g_pool[GG * HD];
__device__ int g_is64;

__device__ __forceinline__ int IDX(const void* p, long long pos) {
    return g_is64 ? (int)((const long long*)p)[pos] : ((const int*)p)[pos];
}

// ---------------- dtype detection (reads first 32KB only) -------------------
__global__ void detect_kernel(const unsigned int* __restrict__ raw) {
    __shared__ int nz;
    if (threadIdx.x == 0) nz = 0;
    __syncthreads();
    int cnt = 0;
    for (int j = threadIdx.x; j < 4096; j += 256)
        if (raw[2 * j + 1] != 0u) cnt++;
    atomicAdd(&nz, cnt);
    __syncthreads();
    if (threadIdx.x == 0) g_is64 = (nz < 64) ? 1 : 0;
}

// ---------------- prep ------------------------------------------------------
// index convert + in-degree histogram (+ gstart init folded in)
__global__ void conv_deg_kernel(const void* __restrict__ ei) {
    int i = blockIdx.x * blockDim.x + threadIdx.x;
    if (i <= GG) g_gstart[i] = NN;
    if (i >= EE) return;
    int s = IDX(ei, i);
    int d = IDX(ei, (long long)EE + i);
    g_src[i] = s;
    g_dst[i] = d;
    atomicAdd(&g_degi[d], 1);
}

// dinv + graph boundary detection fused (both independent over NN)
__global__ void dinv_gstart_kernel(const void* __restrict__ batch) {
    int i = blockIdx.x * blockDim.x + threadIdx.x;
    if (i >= NN) return;
    g_dinv[i] = rsqrtf((float)g_degi[i] + 1.0f);
    int b  = IDX(batch, i);
    int bp = i ? IDX(batch, i - 1) : -1;
    for (int g = bp + 1; g <= b; g++) g_gstart[g] = i;
}

// ---------------- tensor-core GEMM: C[M,128] = A[M,128] @ W[128,128] --------
// a_is_half: A is fp16 (g_hh), raw-copy tile fill; else f32 + convert.
__global__ __launch_bounds__(256) void gemm_tc_kernel(const void* __restrict__ A,
                                                      const float* __restrict__ W,
                                                      int a_is_half) {
    extern __shared__ __half smh[];
    __half* As = smh;                 // [128][PADH]
    __half* Bs = smh + 128 * PADH;    // [128][PADH]  (Bs[k][n])

    int tid = threadIdx.x;
    long long mbase = (long long)blockIdx.x * 128;

    if (a_is_half) {
#pragma unroll
        for (int i = 0; i < 16; i++) {
            int idx = i * 256 + tid;
            int row = idx >> 5, c4 = idx & 31;
            long long grow = mbase + row;
            uint2 v = (grow < NN) ? ((const uint2*)A)[grow * 32 + c4]
                                  : make_uint2(0u, 0u);
            *(uint2*)(As + row * PADH + c4 * 4) = v;
        }
    } else {
#pragma unroll
        for (int i = 0; i < 16; i++) {
            int idx = i * 256 + tid;
            int row = idx >> 5, c4 = idx & 31;
            long long grow = mbase + row;
            float4 v = (grow < NN) ? ((const float4*)A)[grow * 32 + c4]
                                   : make_float4(0.f, 0.f, 0.f, 0.f);
            __half2* dst = (__half2*)(As + row * PADH + c4 * 4);
            dst[0] = __floats2half2_rn(v.x, v.y);
            dst[1] = __floats2half2_rn(v.z, v.w);
        }
    }
#pragma unroll
    for (int i = 0; i < 16; i++) {
        int idx = i * 256 + tid;
        int row = idx >> 5, c4 = idx & 31;
        float4 v = ((const float4*)W)[row * 32 + c4];
        __half2* dst = (__half2*)(Bs + row * PADH + c4 * 4);
        dst[0] = __floats2half2_rn(v.x, v.y);
        dst[1] = __floats2half2_rn(v.z, v.w);
    }
    __syncthreads();

    int wid = tid >> 5, lane = tid & 31;
    int wm = (wid & 3) * 32;
    int wn = (wid >> 2) * 64;

    float acc[2][8][4];
#pragma unroll
    for (int mt = 0; mt < 2; mt++)
#pragma unroll
        for (int nt = 0; nt < 8; nt++)
#pragma unroll
            for (int q = 0; q < 4; q++) acc[mt][nt][q] = 0.f;

#pragma unroll
    for (int kk = 0; kk < 8; kk++) {
        unsigned a[2][4];
#pragma unroll
        for (int mt = 0; mt < 2; mt++) {
            int r = lane & 15, c = (lane >> 4) * 8;
            unsigned addr = (unsigned)__cvta_generic_to_shared(
                As + (wm + mt * 16 + r) * PADH + kk * 16 + c);
            asm volatile("ldmatrix.sync.aligned.m8n8.x4.shared.b16 {%0,%1,%2,%3}, [%4];"
                         : "=r"(a[mt][0]), "=r"(a[mt][1]), "=r"(a[mt][2]), "=r"(a[mt][3])
                         : "r"(addr));
        }
        unsigned b[8][2];
#pragma unroll
        for (int nt2 = 0; nt2 < 4; nt2++) {
            int krow = kk * 16 + ((lane >> 3) & 1) * 8 + (lane & 7);
            int ncol = wn + nt2 * 16 + (lane >> 4) * 8;
            unsigned addr = (unsigned)__cvta_generic_to_shared(Bs + krow * PADH + ncol);
            asm volatile("ldmatrix.sync.aligned.m8n8.x4.trans.shared.b16 {%0,%1,%2,%3}, [%4];"
                         : "=r"(b[nt2 * 2][0]), "=r"(b[nt2 * 2][1]),
                           "=r"(b[nt2 * 2 + 1][0]), "=r"(b[nt2 * 2 + 1][1])
                         : "r"(addr));
        }
#pragma unroll
        for (int mt = 0; mt < 2; mt++)
#pragma unroll
            for (int nt = 0; nt < 8; nt++)
                asm volatile("mma.sync.aligned.m16n8k16.row.col.f32.f16.f16.f32 "
                             "{%0,%1,%2,%3}, {%4,%5,%6,%7}, {%8,%9}, {%0,%1,%2,%3};"
                             : "+f"(acc[mt][nt][0]), "+f"(acc[mt][nt][1]),
                               "+f"(acc[mt][nt][2]), "+f"(acc[mt][nt][3])
                             : "r"(a[mt][0]), "r"(a[mt][1]), "r"(a[mt][2]), "r"(a[mt][3]),
                               "r"(b[nt][0]), "r"(b[nt][1]));
    }

    int r0 = lane >> 2, cq = (lane & 3) * 2;
#pragma unroll
    for (int mt = 0; mt < 2; mt++) {
        long long rowA = mbase + wm + mt * 16 + r0;
        long long rowB = rowA + 8;
#pragma unroll
        for (int nt = 0; nt < 8; nt++) {
            int col = wn + nt * 8 + cq;
            if (rowA < NN) {
                *(float2*)&g_xw[rowA * HD + col] = make_float2(acc[mt][nt][0], acc[mt][nt][1]);
                *(__half2*)&g_xwh[rowA * HD + col] = __floats2half2_rn(acc[mt][nt][0], acc[mt][nt][1]);
            }
            if (rowB < NN) {
                *(float2*)&g_xw[rowB * HD + col] = make_float2(acc[mt][nt][2], acc[mt][nt][3]);
                *(__half2*)&g_xwh[rowB * HD + col] = __floats2half2_rn(acc[mt][nt][2], acc[mt][nt][3]);
            }
        }
    }
}

// ---------------- edge scatter, 2 independent edges per thread (MLP=2) ------
// Each 16-lane slice handles edges e and e+EE/2. All loads issue before math.
__global__ __launch_bounds__(256) void edge_kernel() {
    long long t = (long long)blockIdx.x * 256 + threadIdx.x;
    int e = (int)(t >> 4);                   // 0 .. EE/2-1
    if (e >= EE / 2) return;
    int sub = threadIdx.x & 15;
    int e1 = e + EE / 2;

    int s0 = g_src[e],  d0 = g_dst[e];
    int s1 = g_src[e1], d1 = g_dst[e1];
    // both gathers + all dinv loads in flight before any math
    uint4 v0 = ((const uint4*)g_xwh)[(size_t)s0 * 16 + sub];
    uint4 v1 = ((const uint4*)g_xwh)[(size_t)s1 * 16 + sub];
    float nm0 = __ldg(&g_dinv[s0]) * __ldg(&g_dinv[d0]);
    float nm1 = __ldg(&g_dinv[s1]) * __ldg(&g_dinv[d1]);

    __half2* h0 = (__half2*)&v0;
    __half2* h1 = (__half2*)&v1;
    uint4 a, b;
    __half2* ha = (__half2*)&a;
    __half2* hb = (__half2*)&b;
#pragma unroll
    for (int i = 0; i < 4; i++) {
        float2 f0 = __half22float2(h0[i]);
        float2 f1 = __half22float2(h1[i]);
        ha[i] = __floats2half2_rn(f0.x * nm0, f0.y * nm0);
        hb[i] = __floats2half2_rn(f1.x * nm1, f1.y * nm1);
    }
    __half* p0 = g_aggh + (size_t)d0 * HD + sub * 8;
    __half* p1 = g_aggh + (size_t)d1 * HD + sub * 8;
    asm volatile("red.global.add.noftz.v4.f16x2 [%0], {%1,%2,%3,%4};"
                 :: "l"(p0), "r"(a.x), "r"(a.y), "r"(a.z), "r"(a.w)
                 : "memory");
    asm volatile("red.global.add.noftz.v4.f16x2 [%0], {%1,%2,%3,%4};"
                 :: "l"(p1), "r"(b.x), "r"(b.y), "r"(b.z), "r"(b.w)
                 : "memory");
}

// ---------------- node epilogue: hh = relu(aggh + xw*dinv^2 + b) (fp16 out) -
__global__ void node_kernel(const float* __restrict__ b) {
    int i = blockIdx.x * blockDim.x + threadIdx.x;   // over NN*32 float4s
    int node = i >> 5, q = i & 31;
    float di = g_dinv[node];
    float d2 = di * di;
    uint2 av = ((const uint2*)g_aggh)[i];
    float2 a0 = __half22float2(*(__half2*)&av.x);
    float2 a1 = __half22float2(*(__half2*)&av.y);
    float4 w  = ((const float4*)g_xw)[i];
    float4 bb = ((const float4*)b)[q];
    float hx = fmaxf(fmaf(w.x, d2, a0.x) + bb.x, 0.f);
    float hy = fmaxf(fmaf(w.y, d2, a0.y) + bb.y, 0.f);
    float hz = fmaxf(fmaf(w.z, d2, a1.x) + bb.z, 0.f);
    float hw = fmaxf(fmaf(w.w, d2, a1.y) + bb.w, 0.f);
    uint2 o;
    *(__half2*)&o.x = __floats2half2_rn(hx, hy);
    *(__half2*)&o.y = __floats2half2_rn(hz, hw);
    ((uint2*)g_hh)[i] = o;
}

// ---------------- mean pool over sorted batch (shared-bin, fp16 reads) ------
#define POOL_BLOCKS 320
#define POOL_NODES  125          // 320 * 125 = 40000
__global__ __launch_bounds__(128) void pool_accum_kernel(const void* __restrict__ batch) {
    __shared__ float sh[GG * HD];        // 32 KB; thread t owns column t
    int t = threadIdx.x;
    for (int i = t; i < GG * HD; i += 128) sh[i] = 0.f;
    __syncthreads();
    int start = blockIdx.x * POOL_NODES;
    for (int n = start; n < start + POOL_NODES; n++) {
        int g = IDX(batch, n);
        sh[g * HD + t] += __half2float(g_hh[(size_t)n * HD + t]);
    }
    __syncthreads();
    for (int i = t; i < GG * HD; i += 128) atomicAdd(&g_pool[i], sh[i]);
}

__global__ void pool_final_kernel(float* __restrict__ out) {
    int i = blockIdx.x * blockDim.x + threadIdx.x;
    if (i >= GG * HD) return;
    int g = i >> 7;
    float c = (float)(g_gstart[g + 1] - g_gstart[g]);
    out[i] = g_pool[i] / fmaxf(c, 1.0f);
}

// ---------------- launch -----------------------------------------------------
extern "C" void kernel_launch(void* const* d_in, const int* in_sizes, int n_in,
                              void* d_out, int out_size) {
    const float *x = 0, *W1 = 0, *b1 = 0, *W2 = 0, *b2 = 0;
    const void  *ei = 0, *batch = 0;
    for (int i = 0; i < n_in; i++) {
        long long sz = in_sizes[i];
        if      (sz == (long long)NN * HD) x = (const float*)d_in[i];
        else if (sz == 2LL * EE)           ei = d_in[i];
        else if (sz == NN)                 batch = d_in[i];
        else if (sz == HD * HD) { if (!W1) W1 = (const float*)d_in[i];
                                  else     W2 = (const float*)d_in[i]; }
        else if (sz == HD)      { if (!b1) b1 = (const float*)d_in[i];
                                  else     b2 = (const float*)d_in[i]; }
    }
    float* out = (float*)d_out;

    static cudaStream_t sA = 0;
    static cudaEvent_t ev0 = 0, ev1 = 0, ev2 = 0, ev3 = 0, evZ = 0;
    static void* aggh_addr = 0;
    static void* hh_addr = 0;
    static void* degi_addr = 0;
    static void* pool_addr = 0;
    if (!sA) {
        cudaStreamCreateWithFlags(&sA, cudaStreamNonBlocking);
        cudaEventCreateWithFlags(&ev0, cudaEventDisableTiming);
        cudaEventCreateWithFlags(&ev1, cudaEventDisableTiming);
        cudaEventCreateWithFlags(&ev2, cudaEventDisableTiming);
        cudaEventCreateWithFlags(&ev3, cudaEventDisableTiming);
        cudaEventCreateWithFlags(&evZ, cudaEventDisableTiming);
        cudaGetSymbolAddress(&aggh_addr, g_aggh);
        cudaGetSymbolAddress(&hh_addr, g_hh);
        cudaGetSymbolAddress(&degi_addr, g_degi);
        cudaGetSymbolAddress(&pool_addr, g_pool);
        cudaFuncSetAttribute((const void*)gemm_tc_kernel,
                             cudaFuncAttributeMaxDynamicSharedMemorySize,
                             2 * 128 * PADH * (int)sizeof(__half));
    }

    const int ZBM   = (NN + 255) / 256;       // 157
    const int EB    = (EE + 255) / 256;       // 2500
    const int EDGB  = (EE / 2 * 16) / 256;    // 20000
    const int NODB  = (NN * 32) / 256;        // 5000
    const int GEMMB = (NN + 127) / 128;       // 313
    const int GSM   = 2 * 128 * PADH * (int)sizeof(__half);
    const size_t AGG_BYTES = (size_t)NN * HD * sizeof(__half);

    // fork: sA zeroes everything + runs GEMM1; main runs detect -> prep chain
    cudaEventRecord(ev0, 0);
    cudaStreamWaitEvent(sA, ev0, 0);
    cudaMemsetAsync(degi_addr, 0, NN * sizeof(int), sA);
    cudaMemsetAsync(pool_addr, 0, GG * HD * sizeof(float), sA);
    cudaEventRecord(evZ, sA);                 // degi/pool zeroed
    cudaMemsetAsync(aggh_addr, 0, AGG_BYTES, sA);
    gemm_tc_kernel<<<GEMMB, 256, GSM, sA>>>(x, W1, 0);
    cudaEventRecord(ev1, sA);

    detect_kernel<<<1, 256>>>((const unsigned int*)ei);
    cudaStreamWaitEvent(0, evZ, 0);
    conv_deg_kernel<<<EB, 256>>>(ei);
    dinv_gstart_kernel<<<ZBM, 256>>>(batch);

    // join: layer-1 edge phase
    cudaStreamWaitEvent(0, ev1, 0);
    edge_kernel<<<EDGB, 256>>>();
    node_kernel<<<NODB, 256>>>(b1);
    cudaEventRecord(ev2, 0);

    // fork: re-zero accumulator on sA while main stream runs GEMM2 (fp16 A)
    cudaStreamWaitEvent(sA, ev2, 0);
    cudaMemsetAsync(aggh_addr, 0, AGG_BYTES, sA);
    cudaEventRecord(ev3, sA);
    gemm_tc_kernel<<<GEMMB, 256, GSM>>>(hh_addr, W2, 1);

    // join: layer-2 edge phase
    cudaStreamWaitEvent(0, ev3, 0);
    edge_kernel<<<EDGB, 256>>>();
    node_kernel<<<NODB, 256>>>(b2);

    // pool
    pool_accum_kernel<<<POOL_BLOCKS, 128>>>(batch);
    pool_final_kernel<<<(GG * HD + 255) / 256, 256>>>(out);
}